// round 16
// baseline (speedup 1.0000x reference)
#include <cuda_runtime.h>
#include <cuda_bf16.h>
#include <math.h>
#include <float.h>
#include <stdint.h>

#define NROW 16384
#define DIM  512
#define MARGIN 2.0f
#define EPSV 1e-6f

#if defined(__CUDA_ARCH_FEAT_SM103_ALL) || (defined(__CUDA_ARCH_SPECIFIC__) && (__CUDA_ARCH_SPECIFIC__ == 1030))
#define HAS_TCGEN05 1
#else
#define HAS_TCGEN05 0
#endif

// ---- device scratch ----
__device__ __align__(16) float g_sq[NROW];
__device__ int   g_neg[NROW];
__device__ float g_rowloss[NROW];
__device__ int   g_blkdone;               // rowloss completion counter (self-resetting)
// bf16 PRE-SWIZZLED as 256 tiles of 64 rows x 512 K = 64KB each (SW128 image):
// tile t: 8 slabs of 8KB (64 K-elems each); bo = r*128 + (k&63)*2,
// stored at bo^((bo>>3)&0x70). Linear 64KB bulk copy == SW128 SMEM image.
__device__ __align__(256) uint32_t g_xb[NROW * DIM / 2];

// SMEM layout
#define SMEM_TPTR   0
#define SMEM_FULL0  8            // 3 mbarriers (own B ring complete_tx)
#define SMEM_DONE0  40           // 2 mbarriers (MMA commit, multicast to both)
#define SMEM_DFREE0 72           // 2 mbarriers (own epilogue done with D slot)
#define SMEM_READY0 104          // 2 mbarriers (leader: follower tile-ready)
#define SMEM_SQF0   136          // 8 mbarriers (sq ring complete_tx)
#define SMEM_SQS    1024         // 8 slots x 512B -> ends 5120
#define SMEM_B      8192         // 3 x 65536 -> ends 204800
#define SMEM_TOTAL  204800

#define TMEM_A 0                 // 256 cols: own 128 rows x 512 bf16
#define TMEM_D 256               // 2 x 128 cols f32

#define NTILE 128                // 128-column tiles
#define THREADS 160              // w0 = producer(+MMA on leader), w1-4 = epilogue

#if HAS_TCGEN05
__device__ __forceinline__ uint32_t elect_one() {
    uint32_t p;
    asm volatile("{\n\t.reg .pred p;\n\telect.sync _|p, 0xFFFFFFFF;\n\tselp.b32 %0, 1, 0, p;\n\t}" : "=r"(p));
    return p;
}
#define TCGEN05_ALLOC_CG2(dst, n) \
    asm volatile("tcgen05.alloc.cta_group::2.sync.aligned.shared::cta.b32 [%0], %1;" :: "r"(dst), "r"(n) : "memory")
#define TCGEN05_DEALLOC_CG2(t, n) \
    asm volatile("tcgen05.dealloc.cta_group::2.sync.aligned.b32 %0, %1;" :: "r"(t), "r"(n))
#define TCGEN05_RELINQ_CG2() \
    asm volatile("tcgen05.relinquish_alloc_permit.cta_group::2.sync.aligned;")
#define TCGEN05_WAIT_ST() asm volatile("tcgen05.wait::st.sync.aligned;" ::: "memory")
#define TCGEN05_WAIT_LD() asm volatile("tcgen05.wait::ld.sync.aligned;" ::: "memory")
#define TCGEN05_FENCE_BEFORE() asm volatile("tcgen05.fence::before_thread_sync;" ::: "memory")
#define TCGEN05_FENCE_AFTER()  asm volatile("tcgen05.fence::after_thread_sync;" ::: "memory")
#define FENCE_PROXY_ASYNC() asm volatile("fence.proxy.async;" ::: "memory")
#define MBARRIER_INIT(m, c) \
    asm volatile("mbarrier.init.shared.b64 [%0], %1;" :: "r"(m), "r"(c) : "memory")
#define MBARRIER_ARRIVE(m) \
    asm volatile("mbarrier.arrive.release.cta.shared.b64 _, [%0];" :: "r"(m) : "memory")
#define MBARRIER_EXPECT_TX(m, b) \
    asm volatile("mbarrier.arrive.expect_tx.shared.b64 _, [%0], %1;" :: "r"(m), "r"(b) : "memory")
#define MBARRIER_ARRIVE_LEADER(local_addr) \
    asm volatile("{\n\t.reg .b32 rA;\n\t.reg .b32 z;\n\tmov.b32 z, 0;\n\t" \
        "mapa.shared::cluster.u32 rA, %0, z;\n\t" \
        "mbarrier.arrive.release.cluster.shared::cluster.b64 _, [rA];\n\t}" \
        :: "r"((uint32_t)(local_addr)) : "memory")
#define TCGEN05_COMMIT_MC_CG2(m) \
    asm volatile("tcgen05.commit.cta_group::2.mbarrier::arrive::one.shared::cluster.multicast::cluster.b64 [%0], %1;" \
        :: "r"(m), "h"((uint16_t)3) : "memory")
#define CLUSTER_SYNC() do { \
    asm volatile("barrier.cluster.arrive.aligned;" ::: "memory"); \
    asm volatile("barrier.cluster.wait.aligned;" ::: "memory"); \
} while (0)

#define MBARRIER_WAIT_PARITY(mbar_smem_addr, phase_parity) do { \
    uint32_t _mbar = (uint32_t)(mbar_smem_addr); \
    uint32_t _parity = (uint32_t)(phase_parity); \
    uint32_t _done; \
    asm volatile("{\n\t.reg .pred p;\n\t" \
        "mbarrier.try_wait.parity.acquire.cta.shared::cta.b64 p, [%1], %2;\n\t" \
        "selp.b32 %0, 1, 0, p;\n\t}" : "=r"(_done) : "r"(_mbar), "r"(_parity) : "memory"); \
    if (!_done) { \
        asm volatile("{\n\t.reg .pred P1;\n\t" \
            "WAIT_LOOP_%=:\n\t" \
            "mbarrier.try_wait.parity.acquire.cta.shared::cta.b64 P1, [%0], %1, 0x989680;\n\t" \
            "@P1 bra.uni WAIT_DONE_%=;\n\t" \
            "bra.uni WAIT_LOOP_%=;\n\t" \
            "WAIT_DONE_%=:\n\t}" :: "r"(_mbar), "r"(_parity) : "memory"); \
    } \
} while (0)

#define MBARRIER_WAIT_PARITY_CL(mbar_smem_addr, phase_parity) do { \
    uint32_t _mbar = (uint32_t)(mbar_smem_addr); \
    uint32_t _parity = (uint32_t)(phase_parity); \
    uint32_t _done; \
    asm volatile("{\n\t.reg .pred p;\n\t" \
        "mbarrier.try_wait.parity.acquire.cluster.shared::cta.b64 p, [%1], %2;\n\t" \
        "selp.b32 %0, 1, 0, p;\n\t}" : "=r"(_done) : "r"(_mbar), "r"(_parity) : "memory"); \
    if (!_done) { \
        asm volatile("{\n\t.reg .pred P1;\n\t" \
            "WAIT_LOOP_%=:\n\t" \
            "mbarrier.try_wait.parity.acquire.cluster.shared::cta.b64 P1, [%0], %1, 0x989680;\n\t" \
            "@P1 bra.uni WAIT_DONE_%=;\n\t" \
            "bra.uni WAIT_LOOP_%=;\n\t" \
            "WAIT_DONE_%=:\n\t}" :: "r"(_mbar), "r"(_parity) : "memory"); \
    } \
} while (0)

#define TCGEN05_ST_X32(tmem_addr, r) \
    asm volatile("tcgen05.st.sync.aligned.32x32b.x32.b32 [%0], " \
        "{%1, %2, %3, %4, %5, %6, %7, %8, %9, %10, %11, %12, %13, %14, %15, %16, " \
        "%17, %18, %19, %20, %21, %22, %23, %24, %25, %26, %27, %28, %29, %30, %31, %32};" \
        :: "r"(tmem_addr), \
           "r"((r)[0]),"r"((r)[1]),"r"((r)[2]),"r"((r)[3]),"r"((r)[4]),"r"((r)[5]),"r"((r)[6]),"r"((r)[7]), \
           "r"((r)[8]),"r"((r)[9]),"r"((r)[10]),"r"((r)[11]),"r"((r)[12]),"r"((r)[13]),"r"((r)[14]),"r"((r)[15]), \
           "r"((r)[16]),"r"((r)[17]),"r"((r)[18]),"r"((r)[19]),"r"((r)[20]),"r"((r)[21]),"r"((r)[22]),"r"((r)[23]), \
           "r"((r)[24]),"r"((r)[25]),"r"((r)[26]),"r"((r)[27]),"r"((r)[28]),"r"((r)[29]),"r"((r)[30]),"r"((r)[31]) \
        : "memory")

#define TCGEN05_LD_X32(r, tmem_addr) \
    asm volatile("tcgen05.ld.sync.aligned.32x32b.x32.b32 " \
        "{%0, %1, %2, %3, %4, %5, %6, %7, %8, %9, %10, %11, %12, %13, %14, %15, " \
        "%16, %17, %18, %19, %20, %21, %22, %23, %24, %25, %26, %27, %28, %29, %30, %31}, [%32];" \
        : "=r"((r)[0]),"=r"((r)[1]),"=r"((r)[2]),"=r"((r)[3]),"=r"((r)[4]),"=r"((r)[5]),"=r"((r)[6]),"=r"((r)[7]), \
          "=r"((r)[8]),"=r"((r)[9]),"=r"((r)[10]),"=r"((r)[11]),"=r"((r)[12]),"=r"((r)[13]),"=r"((r)[14]),"=r"((r)[15]), \
          "=r"((r)[16]),"=r"((r)[17]),"=r"((r)[18]),"=r"((r)[19]),"=r"((r)[20]),"=r"((r)[21]),"=r"((r)[22]),"=r"((r)[23]), \
          "=r"((r)[24]),"=r"((r)[25]),"=r"((r)[26]),"=r"((r)[27]),"=r"((r)[28]),"=r"((r)[29]),"=r"((r)[30]),"=r"((r)[31]) \
        : "r"(tmem_addr))

__device__ __forceinline__ void bulk_g2s(uint32_t dst, const void* src, uint32_t bytes, uint32_t mbar) {
    asm volatile("cp.async.bulk.shared::cta.global.mbarrier::complete_tx::bytes [%0], [%1], %2, [%3];"
                 :: "r"(dst), "l"(src), "r"(bytes), "r"(mbar) : "memory");
}

// cg2 TS-mode bf16 MMA: A in (each CTA's own) TMEM, B via SMEM descriptor
__device__ __forceinline__ void mma_f16_ts_cg2(uint32_t d_tmem, uint32_t a_tmem,
                                               uint64_t b_desc, uint32_t idesc, bool acc) {
    uint32_t en = acc ? 1u : 0u;
    asm volatile("{\n\t.reg .pred p;\n\tsetp.ne.u32 p, %5, 0;\n\t"
        "tcgen05.mma.cta_group::2.kind::f16 [%0], [%1], %2, %3, "
        "{%4, %4, %4, %4, %4, %4, %4, %4}, p;\n\t}"
        :: "r"(d_tmem), "r"(a_tmem), "l"(b_desc), "r"(idesc), "r"(0u), "r"(en)
        : "memory");
}

__device__ __forceinline__ uint64_t make_desc(uint32_t addr) {
    return (uint64_t(2) << 61) | (uint64_t(1) << 46) | (uint64_t(64) << 32)
         | (uint64_t(1) << 16) | ((addr >> 4) & 0x3FFF);
}

// idesc: F32 accum, bf16 A/B, M=256 (16<<24), N=128 (16<<17)
#define MMA_IDESC ((16u << 24) | (16u << 17) | (1u << 10) | (1u << 7) | (1u << 4))
#endif  // HAS_TCGEN05

__device__ __forceinline__ uint32_t smem_u32(const void* p) {
    uint32_t a;
    asm("{ .reg .u64 t; cvta.to.shared.u64 t, %1; cvt.u32.u64 %0, t; }" : "=r"(a) : "l"(p));
    return a;
}

// ============================================================
// Kernel 0: fp32 -> pre-swizzled 64-row bf16 tiles + exact row norms
// ============================================================
__global__ __launch_bounds__(128) void cvtsq_kernel(const float* __restrict__ X) {
    int row = blockIdx.x;
    int t = threadIdx.x;
    float4 v = *(const float4*)(X + (size_t)row * DIM + t * 4);
    uint32_t lo, hi;
    asm("cvt.rn.bf16x2.f32 %0, %1, %2;" : "=r"(lo) : "f"(v.y), "f"(v.x));
    asm("cvt.rn.bf16x2.f32 %0, %1, %2;" : "=r"(hi) : "f"(v.w), "f"(v.z));
    int tile = row >> 6, r = row & 63;
    int k = t * 4;
    uint32_t bo = (uint32_t)(r * 128 + (k & 63) * 2);
    uint32_t sw = bo ^ ((bo >> 3) & 0x70);
    *(uint2*)((char*)g_xb + (size_t)tile * 65536 + (size_t)(k >> 6) * 8192 + sw)
        = make_uint2(lo, hi);
    float s = v.x * v.x + v.y * v.y + v.z * v.z + v.w * v.w;
#pragma unroll
    for (int o = 16; o > 0; o >>= 1) s += __shfl_down_sync(0xffffffffu, s, o);
    __shared__ float ws[4];
    if ((t & 31) == 0) ws[t >> 5] = s;
    __syncthreads();
    if (t == 0) g_sq[row] = ws[0] + ws[1] + ws[2] + ws[3];
}

// ============================================================
// Kernel 1: cg2 TS-mode bf16 GEMM, N=128 tiles (M=256 x N=128),
// 2-deep 128-col TMEM D ring, 3-deep 64KB B ring, 8-deep sq ring.
// 64 clusters x 2 CTAs x 160 threads. Each CTA: 128 A rows in OWN
// TMEM; per tile u, rank r bulk-loads B rows [u*128 + r*64, +64)
// (= g_xb tile 2u+r, one 64KB bulk). Leader issues 32 cg2 MMAs
// (M=256,N=128,K=16 each) -> D slot u&1; commit multicast.
// Epilogue: wait done -> LDTM 2x64 cols -> early dfree -> screen.
// ============================================================
__global__ __launch_bounds__(THREADS, 1) __cluster_dims__(2, 1, 1)
void mma_topk_kernel() {
    extern __shared__ char smem[];
    const uint32_t smem_base = smem_u32(smem);
    const int tid = threadIdx.x;
    const int rowBase = blockIdx.x * 128;
    const char* xb = (const char*)g_xb;

#if HAS_TCGEN05
    const int wid = tid >> 5;
    const int lane = tid & 31;
    const bool is_prod = (wid == 0);
    const int rank = blockIdx.x & 1;
    const int smsp = wid & 3;
    const int row = smsp * 32 + lane;

    if (is_prod) {
        TCGEN05_ALLOC_CG2(smem_base + SMEM_TPTR, 512);
        TCGEN05_RELINQ_CG2();
    }
    if (tid == 0) {
#pragma unroll
        for (int s = 0; s < 3; ++s) MBARRIER_INIT(smem_base + SMEM_FULL0 + s * 8, 1);
#pragma unroll
        for (int s = 0; s < 2; ++s) {
            MBARRIER_INIT(smem_base + SMEM_DONE0 + s * 8, 1);
            MBARRIER_INIT(smem_base + SMEM_DFREE0 + s * 8, 4);
            MBARRIER_INIT(smem_base + SMEM_READY0 + s * 8, 1);
        }
#pragma unroll
        for (int s = 0; s < 8; ++s) MBARRIER_INIT(smem_base + SMEM_SQF0 + s * 8, 1);
    }
    __syncthreads();
    uint32_t tmem_base;
    asm volatile("ld.shared.b32 %0, [%1];" : "=r"(tmem_base) : "r"(smem_base + SMEM_TPTR));

    // ---- A fill: epilogue warps store own 128 rows x 512 bf16 to own TMEM,
    //      de-swizzling 16B granules from the pre-swizzled g_xb image ----
    if (!is_prod) {
        const int R = rowBase + row;
        const int tt = R >> 6, r = R & 63;
        const char* tbase = xb + (size_t)tt * 65536;
        uint32_t wo = (uint32_t)smsp << 21;
#pragma unroll
        for (int c8 = 0; c8 < 8; ++c8) {
            uint32_t rg[32];
#pragma unroll
            for (int u = 0; u < 8; ++u) {
                int g = c8 * 8 + u;
                uint32_t bo = (uint32_t)(r * 128 + (g & 7) * 16);
                uint32_t sw = bo ^ ((bo >> 3) & 0x70);
                uint4 v = *(const uint4*)(tbase + (size_t)(g >> 3) * 8192 + sw);
                rg[u * 4 + 0] = v.x; rg[u * 4 + 1] = v.y;
                rg[u * 4 + 2] = v.z; rg[u * 4 + 3] = v.w;
            }
            TCGEN05_ST_X32(tmem_base + TMEM_A + c8 * 32 + wo, rg);
        }
        TCGEN05_WAIT_ST();
        TCGEN05_FENCE_BEFORE();
    } else {
        // prologue: B tiles 0,1 (own 64-row halves) + sq 0,1
        if (elect_one()) {
#pragma unroll
            for (int pt = 0; pt < 2; ++pt) {
                uint32_t fb = smem_base + SMEM_FULL0 + pt * 8;
                MBARRIER_EXPECT_TX(fb, 65536);
                bulk_g2s(smem_base + SMEM_B + pt * 65536,
                         xb + (size_t)(2 * pt + rank) * 65536, 65536, fb);
                uint32_t qb = smem_base + SMEM_SQF0 + pt * 8;
                MBARRIER_EXPECT_TX(qb, 512);
                bulk_g2s(smem_base + SMEM_SQS + pt * 512, (const char*)g_sq + pt * 512, 512, qb);
            }
        }
    }
    __syncthreads();
    CLUSTER_SYNC();   // both CTAs' A in TMEM + mbarriers visible before any cg2 MMA

    if (is_prod) {
        for (int u = 0; u < NTILE; ++u) {
            const int ds = u & 1;
            MBARRIER_WAIT_PARITY(smem_base + SMEM_FULL0 + (u % 3) * 8, (u / 3) & 1);
            if (u >= 2)
                MBARRIER_WAIT_PARITY(smem_base + SMEM_DFREE0 + ds * 8, ((u - 2) >> 1) & 1);

            if (rank == 1) {
                TCGEN05_FENCE_AFTER();
                if (elect_one())
                    MBARRIER_ARRIVE_LEADER(smem_base + SMEM_READY0 + ds * 8);
            } else {
                MBARRIER_WAIT_PARITY_CL(smem_base + SMEM_READY0 + ds * 8, (u >> 1) & 1);
                TCGEN05_FENCE_AFTER();
                if (elect_one()) {
                    uint64_t bdesc = make_desc(smem_base + SMEM_B + (u % 3) * 65536);
                    uint32_t dtm = tmem_base + TMEM_D + ds * 128;
#pragma unroll
                    for (int c = 0; c < 32; ++c) {
                        uint64_t boff = (uint64_t)((c >> 2) * 512 + (c & 3) * 2);
                        mma_f16_ts_cg2(dtm, tmem_base + TMEM_A + c * 8,
                                       bdesc + boff, MMA_IDESC, c > 0);
                    }
                    TCGEN05_COMMIT_MC_CG2(smem_base + SMEM_DONE0 + ds * 8);
                }
            }

            // recycle: B(u+2) -> slot (u+2)%3 (last read by MMA(u-1) -> done(u-1));
            //          sq(u+2) -> slot (u+2)&7 (epi(u-6) done via dfree(u-2))
            if (u + 2 < NTILE) {
                if (u >= 1)
                    MBARRIER_WAIT_PARITY(smem_base + SMEM_DONE0 + ((u - 1) & 1) * 8,
                                         ((u - 1) >> 1) & 1);
                if (elect_one()) {
                    int s2 = (u + 2) % 3;
                    uint32_t fb = smem_base + SMEM_FULL0 + s2 * 8;
                    MBARRIER_EXPECT_TX(fb, 65536);
                    bulk_g2s(smem_base + SMEM_B + s2 * 65536,
                             xb + (size_t)(2 * (u + 2) + rank) * 65536, 65536, fb);
                    int q2 = (u + 2) & 7;
                    uint32_t qb = smem_base + SMEM_SQF0 + q2 * 8;
                    MBARRIER_EXPECT_TX(qb, 512);
                    bulk_g2s(smem_base + SMEM_SQS + q2 * 512,
                             (const char*)g_sq + (size_t)(u + 2) * 512, 512, qb);
                }
            }
        }
    } else {
        // ---- epilogue warps: per-thread (one row) top-3 over all tiles ----
        float v0 = FLT_MAX, v1 = FLT_MAX, v2 = FLT_MAX;
        int   i0 = 0, i1 = 0, i2 = 0;
        for (int u = 0; u < NTILE; ++u) {
            const int ds = u & 1;
            MBARRIER_WAIT_PARITY(smem_base + SMEM_DONE0 + ds * 8, (u >> 1) & 1);
            TCGEN05_FENCE_AFTER();
            MBARRIER_WAIT_PARITY(smem_base + SMEM_SQF0 + (u & 7) * 8, (u >> 3) & 1);
            const float* sqt = (const float*)(smem + SMEM_SQS + (u & 7) * 512);
            const uint32_t dtm = tmem_base + TMEM_D + ds * 128;
#pragma unroll
            for (int h = 0; h < 2; ++h) {
                uint32_t dr[64];
                TCGEN05_LD_X32(dr, dtm + h * 64);
                TCGEN05_LD_X32(dr + 32, dtm + h * 64 + 32);
                TCGEN05_WAIT_LD();
                if (h == 1) {   // all 128 cols read: release D slot early
                    TCGEN05_FENCE_BEFORE();
                    if (lane == 0) MBARRIER_ARRIVE(smem_base + SMEM_DFREE0 + ds * 8);
                }
                const int colBase = u * 128 + h * 64;
                const float* sqh = sqt + h * 64;
#pragma unroll
                for (int g = 0; g < 4; ++g) {
                    float key[16];
#pragma unroll
                    for (int c = 0; c < 16; ++c)
                        key[c] = fmaf(-2.f, __uint_as_float(dr[g * 16 + c]), sqh[g * 16 + c]);
                    float t8[8];
#pragma unroll
                    for (int c = 0; c < 8; ++c) t8[c] = fminf(key[c], key[c + 8]);
                    float t4a = fminf(t8[0], t8[4]), t4b = fminf(t8[1], t8[5]);
                    float t4c = fminf(t8[2], t8[6]), t4d = fminf(t8[3], t8[7]);
                    float mn = fminf(fminf(t4a, t4b), fminf(t4c, t4d));
                    if (mn < v2) {   // rare: exact ordered insert, ascending cols
#pragma unroll
                        for (int c = 0; c < 16; ++c) {
                            float k = key[c];
                            int col = colBase + g * 16 + c;
                            if (k < v2) {
                                if (k < v1) {
                                    v2 = v1; i2 = i1;
                                    if (k < v0) { v1 = v0; i1 = i0; v0 = k; i0 = col; }
                                    else        { v1 = k; i1 = col; }
                                } else { v2 = k; i2 = col; }
                            }
                        }
                    }
                }
            }
        }
        g_neg[rowBase + row] = i2;
    }

    __syncthreads();
    CLUSTER_SYNC();   // peer MMA done reading my SMEM/TMEM before teardown
    if (is_prod) TCGEN05_DEALLOC_CG2(tmem_base, 512);
    CLUSTER_SYNC();

#else  // ---------------- SIMT fallback (non-'a' pass) ----------------
    // Reads the pre-swizzled 64-row-tile g_xb layout (per-4B de-swizzle).
    float* As = (float*)(smem);
    float* Bs = (float*)(smem + 4096);
    float* mv = (float*)(smem + 12288);
    int*   mi = (int*)(smem + 36864);
    const int tx = tid & 15, ty = tid >> 4;
    const bool act = (tid < 128);

    for (int half = 0; half < 2; ++half) {
        const int rh = rowBase + half * 64;
        float tv[8][3]; int tii[8][3];
#pragma unroll
        for (int i = 0; i < 8; ++i)
#pragma unroll
            for (int q = 0; q < 3; ++q) { tv[i][q] = FLT_MAX; tii[i][q] = 0x7fffffff; }

        for (int jt = 0; jt < NROW / 128; ++jt) {
            const int colBase = jt * 128;
            float c[8][8];
#pragma unroll
            for (int i = 0; i < 8; ++i)
#pragma unroll
                for (int j = 0; j < 8; ++j) c[i][j] = 0.f;

            for (int kt = 0; kt < DIM; kt += 16) {
                __syncthreads();
                if (act) {
#pragma unroll
                    for (int l = 0; l < 4; ++l) {
                        int f = tid + l * 128;
                        int r = f >> 3, uu = f & 7;
                        int R = rh + r, kk = kt + 2 * uu;
                        uint32_t bo = (uint32_t)((R & 63) * 128 + (kk & 63) * 2);
                        uint32_t sw = bo ^ ((bo >> 3) & 0x70);
                        uint32_t w = *(const uint32_t*)(xb + (size_t)(R >> 6) * 65536
                                                        + (size_t)(kk >> 6) * 8192 + sw);
                        __nv_bfloat162 b2 = *(__nv_bfloat162*)&w;
                        float2 f2 = __bfloat1622float2(b2);
                        As[(2 * uu + 0) * 64 + r] = f2.x;
                        As[(2 * uu + 1) * 64 + r] = f2.y;
                    }
#pragma unroll
                    for (int l = 0; l < 8; ++l) {
                        int f = tid + l * 128;
                        int r = f >> 3, uu = f & 7;
                        int R = colBase + r, kk = kt + 2 * uu;
                        uint32_t bo = (uint32_t)((R & 63) * 128 + (kk & 63) * 2);
                        uint32_t sw = bo ^ ((bo >> 3) & 0x70);
                        uint32_t w = *(const uint32_t*)(xb + (size_t)(R >> 6) * 65536
                                                        + (size_t)(kk >> 6) * 8192 + sw);
                        __nv_bfloat162 b2 = *(__nv_bfloat162*)&w;
                        float2 f2 = __bfloat1622float2(b2);
                        Bs[(2 * uu + 0) * 128 + r] = f2.x;
                        Bs[(2 * uu + 1) * 128 + r] = f2.y;
                    }
                }
                __syncthreads();
                if (act) {
#pragma unroll
                    for (int kk = 0; kk < 16; ++kk) {
                        float a[8], b[8];
#pragma unroll
                        for (int i = 0; i < 8; ++i) a[i] = As[kk * 64 + ty * 8 + i];
#pragma unroll
                        for (int j = 0; j < 8; ++j) b[j] = Bs[kk * 128 + tx * 8 + j];
#pragma unroll
                        for (int i = 0; i < 8; ++i)
#pragma unroll
                            for (int j = 0; j < 8; ++j) c[i][j] += a[i] * b[j];
                    }
                }
            }
            if (act) {
#pragma unroll
                for (int j = 0; j < 8; ++j) {
                    int col = colBase + tx * 8 + j;
                    float sqc = g_sq[col];
#pragma unroll
                    for (int i = 0; i < 8; ++i) {
                        float d2 = fmaf(-2.f, c[i][j], sqc);
                        bool b2c = (d2 < tv[i][2]) || (d2 == tv[i][2] && col < tii[i][2]);
                        if (b2c) {
                            bool b1c = (d2 < tv[i][1]) || (d2 == tv[i][1] && col < tii[i][1]);
                            bool b0c = (d2 < tv[i][0]) || (d2 == tv[i][0] && col < tii[i][0]);
                            if (b0c) {
                                tv[i][2] = tv[i][1]; tii[i][2] = tii[i][1];
                                tv[i][1] = tv[i][0]; tii[i][1] = tii[i][0];
                                tv[i][0] = d2;       tii[i][0] = col;
                            } else if (b1c) {
                                tv[i][2] = tv[i][1]; tii[i][2] = tii[i][1];
                                tv[i][1] = d2;       tii[i][1] = col;
                            } else { tv[i][2] = d2; tii[i][2] = col; }
                        }
                    }
                }
            }
        }

        __syncthreads();
        if (act) {
#pragma unroll
            for (int i = 0; i < 8; ++i)
#pragma unroll
                for (int q = 0; q < 3; ++q) {
                    mv[(ty * 8 + i) * 48 + tx * 3 + q] = tv[i][q];
                    mi[(ty * 8 + i) * 48 + tx * 3 + q] = tii[i][q];
                }
        }
        __syncthreads();
        if (tid < 64) {
            float w0 = FLT_MAX, w1 = FLT_MAX, w2 = FLT_MAX;
            int   j0 = 0x7fffffff, j1 = 0x7fffffff, j2 = 0x7fffffff;
            for (int cnd = 0; cnd < 48; ++cnd) {
                float d = mv[tid * 48 + cnd];
                int   ix = mi[tid * 48 + cnd];
                bool b2c = (d < w2) || (d == w2 && ix < j2);
                if (b2c) {
                    bool b1c = (d < w1) || (d == w1 && ix < j1);
                    bool b0c = (d < w0) || (d == w0 && ix < j0);
                    if (b0c)      { w2 = w1; j2 = j1; w1 = w0; j1 = j0; w0 = d; j0 = ix; }
                    else if (b1c) { w2 = w1; j2 = j1; w1 = d; j1 = ix; }
                    else          { w2 = d;  j2 = ix; }
                }
            }
            g_neg[rh + tid] = j2;
        }
        __syncthreads();
    }
#endif
}

// ============================================================
// Kernel 2: per-row triplet loss (one warp per row) + fused
// deterministic mean reduction in the last-arriving block.
// ============================================================
__global__ __launch_bounds__(256) void rowloss_kernel(const float* __restrict__ X,
                                                      const float* __restrict__ P,
                                                      float* __restrict__ out) {
    int warp = threadIdx.x >> 5;
    int lane = threadIdx.x & 31;
    int row = blockIdx.x * 8 + warp;
    const float4* xr = (const float4*)(X + (size_t)row * DIM);
    const float4* pr = (const float4*)(P + (size_t)row * DIM);
    const float4* nr = (const float4*)(X + (size_t)g_neg[row] * DIM);
    float sap = 0.f, san = 0.f;
#pragma unroll
    for (int i = 0; i < 4; ++i) {
        float4 x = xr[lane + 32 * i];
        float4 p = pr[lane + 32 * i];
        float4 v = nr[lane + 32 * i];
        float d;
        d = x.x - p.x + EPSV; sap += d * d;
        d = x.y - p.y + EPSV; sap += d * d;
        d = x.z - p.z + EPSV; sap += d * d;
        d = x.w - p.w + EPSV; sap += d * d;
        d = x.x - v.x + EPSV; san += d * d;
        d = x.y - v.y + EPSV; san += d * d;
        d = x.z - v.z + EPSV; san += d * d;
        d = x.w - v.w + EPSV; san += d * d;
    }
#pragma unroll
    for (int o = 16; o > 0; o >>= 1) {
        sap += __shfl_down_sync(0xffffffffu, sap, o);
        san += __shfl_down_sync(0xffffffffu, san, o);
    }
    if (lane == 0)
        g_rowloss[row] = fmaxf(sqrtf(sap) - sqrtf(san) + MARGIN, 0.f);

    __shared__ bool s_last;
    __threadfence();
    __syncthreads();
    if (threadIdx.x == 0) {
        int done = atomicAdd(&g_blkdone, 1);
        s_last = (done == gridDim.x - 1);
    }
    __syncthreads();
    if (s_last) {
        int t = threadIdx.x;
        float s = 0.f;
        for (int i = t; i < NROW; i += 256) s += g_rowloss[i];
#pragma unroll
        for (int o = 16; o > 0; o >>= 1) s += __shfl_down_sync(0xffffffffu, s, o);
        __shared__ float ws[8];
        if ((t & 31) == 0) ws[t >> 5] = s;
        __syncthreads();
        if (t == 0) {
            float tot = 0.f;
#pragma unroll
            for (int w = 0; w < 8; ++w) tot += ws[w];
            out[0] = tot / (float)NROW;
            g_blkdone = 0;      // reset for next graph replay
        }
    }
}

extern "C" void kernel_launch(void* const* d_in, const int* in_sizes, int n_in,
                              void* d_out, int out_size) {
    const float* X = (const float*)d_in[0];   // inputs  [16384, 512] f32
    const float* P = (const float*)d_in[1];   // positive[16384, 512] f32
    float* out = (float*)d_out;

    cudaFuncSetAttribute(mma_topk_kernel,
                         cudaFuncAttributeMaxDynamicSharedMemorySize, SMEM_TOTAL);

    cvtsq_kernel<<<NROW, 128>>>(X);
    mma_topk_kernel<<<128, THREADS, SMEM_TOTAL>>>();
    rowloss_kernel<<<NROW / 8, 256>>>(X, P, out);
}

// round 17
// speedup vs baseline: 1.0502x; 1.0502x over previous
#include <cuda_runtime.h>
#include <cuda_bf16.h>
#include <math.h>
#include <float.h>
#include <stdint.h>

#define NROW 16384
#define DIM  512
#define MARGIN 2.0f
#define EPSV 1e-6f

#if defined(__CUDA_ARCH_FEAT_SM103_ALL) || (defined(__CUDA_ARCH_SPECIFIC__) && (__CUDA_ARCH_SPECIFIC__ == 1030))
#define HAS_TCGEN05 1
#else
#define HAS_TCGEN05 0
#endif

// ---- device scratch ----
__device__ __align__(16) float g_sq[NROW];
__device__ int   g_neg[NROW];
__device__ float g_rowloss[NROW];
__device__ int   g_blkdone;               // rowloss completion counter (self-resetting)
// bf16 PRE-SWIZZLED as 512 tiles of 32 rows x 512 K = 32KB each (SW128 image):
// tile t: 8 slabs of 4KB (64 K-elems each); bo = r*128 + (k&63)*2,
// stored at bo^((bo>>3)&0x70). 16B granules stay contiguous under SW128.
__device__ __align__(256) uint32_t g_xb[NROW * DIM / 2];

// SMEM layout (A in TMEM; whole sq resident; 4-deep B ring)
#define SMEM_TPTR   0
#define SMEM_FULL0  8            // 4 mbarriers (own B ring complete_tx)
#define SMEM_DONE0  40           // 4 mbarriers (MMA commit, multicast to both)
#define SMEM_DFREE0 72           // 4 mbarriers (own epilogue done with D slot)
#define SMEM_READY0 104          // 4 mbarriers (leader: follower tile-ready)
#define SMEM_SQFULL 136          // 1 mbarrier  (whole-sq load complete)
#define SMEM_SQ     1024         // 16384 floats = 65536 B -> ends 66560
#define SMEM_B      66560        // 4 x 32768 -> ends 197632
#define SMEM_TOTAL  197632

#define TMEM_A 0                 // 256 cols: own 128 rows x 512 bf16
#define TMEM_D 256               // 4 x 64 cols f32

#define NTILE 256
#define THREADS 160              // w0 = producer(+MMA on leader), w1-4 = epilogue

#if HAS_TCGEN05
__device__ __forceinline__ uint32_t elect_one() {
    uint32_t p;
    asm volatile("{\n\t.reg .pred p;\n\telect.sync _|p, 0xFFFFFFFF;\n\tselp.b32 %0, 1, 0, p;\n\t}" : "=r"(p));
    return p;
}
#define TCGEN05_ALLOC_CG2(dst, n) \
    asm volatile("tcgen05.alloc.cta_group::2.sync.aligned.shared::cta.b32 [%0], %1;" :: "r"(dst), "r"(n) : "memory")
#define TCGEN05_DEALLOC_CG2(t, n) \
    asm volatile("tcgen05.dealloc.cta_group::2.sync.aligned.b32 %0, %1;" :: "r"(t), "r"(n))
#define TCGEN05_RELINQ_CG2() \
    asm volatile("tcgen05.relinquish_alloc_permit.cta_group::2.sync.aligned;")
#define TCGEN05_WAIT_ST() asm volatile("tcgen05.wait::st.sync.aligned;" ::: "memory")
#define TCGEN05_WAIT_LD() asm volatile("tcgen05.wait::ld.sync.aligned;" ::: "memory")
#define TCGEN05_FENCE_BEFORE() asm volatile("tcgen05.fence::before_thread_sync;" ::: "memory")
#define TCGEN05_FENCE_AFTER()  asm volatile("tcgen05.fence::after_thread_sync;" ::: "memory")
#define FENCE_PROXY_ASYNC() asm volatile("fence.proxy.async;" ::: "memory")
#define MBARRIER_INIT(m, c) \
    asm volatile("mbarrier.init.shared.b64 [%0], %1;" :: "r"(m), "r"(c) : "memory")
#define MBARRIER_ARRIVE(m) \
    asm volatile("mbarrier.arrive.release.cta.shared.b64 _, [%0];" :: "r"(m) : "memory")
#define MBARRIER_EXPECT_TX(m, b) \
    asm volatile("mbarrier.arrive.expect_tx.shared.b64 _, [%0], %1;" :: "r"(m), "r"(b) : "memory")
#define MBARRIER_ARRIVE_LEADER(local_addr) \
    asm volatile("{\n\t.reg .b32 rA;\n\t.reg .b32 z;\n\tmov.b32 z, 0;\n\t" \
        "mapa.shared::cluster.u32 rA, %0, z;\n\t" \
        "mbarrier.arrive.release.cluster.shared::cluster.b64 _, [rA];\n\t}" \
        :: "r"((uint32_t)(local_addr)) : "memory")
#define TCGEN05_COMMIT_MC_CG2(m) \
    asm volatile("tcgen05.commit.cta_group::2.mbarrier::arrive::one.shared::cluster.multicast::cluster.b64 [%0], %1;" \
        :: "r"(m), "h"((uint16_t)3) : "memory")
#define CLUSTER_SYNC() do { \
    asm volatile("barrier.cluster.arrive.aligned;" ::: "memory"); \
    asm volatile("barrier.cluster.wait.aligned;" ::: "memory"); \
} while (0)

#define MBARRIER_WAIT_PARITY(mbar_smem_addr, phase_parity) do { \
    uint32_t _mbar = (uint32_t)(mbar_smem_addr); \
    uint32_t _parity = (uint32_t)(phase_parity); \
    uint32_t _done; \
    asm volatile("{\n\t.reg .pred p;\n\t" \
        "mbarrier.try_wait.parity.acquire.cta.shared::cta.b64 p, [%1], %2;\n\t" \
        "selp.b32 %0, 1, 0, p;\n\t}" : "=r"(_done) : "r"(_mbar), "r"(_parity) : "memory"); \
    if (!_done) { \
        asm volatile("{\n\t.reg .pred P1;\n\t" \
            "WAIT_LOOP_%=:\n\t" \
            "mbarrier.try_wait.parity.acquire.cta.shared::cta.b64 P1, [%0], %1, 0x989680;\n\t" \
            "@P1 bra.uni WAIT_DONE_%=;\n\t" \
            "bra.uni WAIT_LOOP_%=;\n\t" \
            "WAIT_DONE_%=:\n\t}" :: "r"(_mbar), "r"(_parity) : "memory"); \
    } \
} while (0)

#define MBARRIER_WAIT_PARITY_CL(mbar_smem_addr, phase_parity) do { \
    uint32_t _mbar = (uint32_t)(mbar_smem_addr); \
    uint32_t _parity = (uint32_t)(phase_parity); \
    uint32_t _done; \
    asm volatile("{\n\t.reg .pred p;\n\t" \
        "mbarrier.try_wait.parity.acquire.cluster.shared::cta.b64 p, [%1], %2;\n\t" \
        "selp.b32 %0, 1, 0, p;\n\t}" : "=r"(_done) : "r"(_mbar), "r"(_parity) : "memory"); \
    if (!_done) { \
        asm volatile("{\n\t.reg .pred P1;\n\t" \
            "WAIT_LOOP_%=:\n\t" \
            "mbarrier.try_wait.parity.acquire.cluster.shared::cta.b64 P1, [%0], %1, 0x989680;\n\t" \
            "@P1 bra.uni WAIT_DONE_%=;\n\t" \
            "bra.uni WAIT_LOOP_%=;\n\t" \
            "WAIT_DONE_%=:\n\t}" :: "r"(_mbar), "r"(_parity) : "memory"); \
    } \
} while (0)

#define TCGEN05_ST_X32(tmem_addr, r) \
    asm volatile("tcgen05.st.sync.aligned.32x32b.x32.b32 [%0], " \
        "{%1, %2, %3, %4, %5, %6, %7, %8, %9, %10, %11, %12, %13, %14, %15, %16, " \
        "%17, %18, %19, %20, %21, %22, %23, %24, %25, %26, %27, %28, %29, %30, %31, %32};" \
        :: "r"(tmem_addr), \
           "r"((r)[0]),"r"((r)[1]),"r"((r)[2]),"r"((r)[3]),"r"((r)[4]),"r"((r)[5]),"r"((r)[6]),"r"((r)[7]), \
           "r"((r)[8]),"r"((r)[9]),"r"((r)[10]),"r"((r)[11]),"r"((r)[12]),"r"((r)[13]),"r"((r)[14]),"r"((r)[15]), \
           "r"((r)[16]),"r"((r)[17]),"r"((r)[18]),"r"((r)[19]),"r"((r)[20]),"r"((r)[21]),"r"((r)[22]),"r"((r)[23]), \
           "r"((r)[24]),"r"((r)[25]),"r"((r)[26]),"r"((r)[27]),"r"((r)[28]),"r"((r)[29]),"r"((r)[30]),"r"((r)[31]) \
        : "memory")

#define TCGEN05_LD_X32(r, tmem_addr) \
    asm volatile("tcgen05.ld.sync.aligned.32x32b.x32.b32 " \
        "{%0, %1, %2, %3, %4, %5, %6, %7, %8, %9, %10, %11, %12, %13, %14, %15, " \
        "%16, %17, %18, %19, %20, %21, %22, %23, %24, %25, %26, %27, %28, %29, %30, %31}, [%32];" \
        : "=r"((r)[0]),"=r"((r)[1]),"=r"((r)[2]),"=r"((r)[3]),"=r"((r)[4]),"=r"((r)[5]),"=r"((r)[6]),"=r"((r)[7]), \
          "=r"((r)[8]),"=r"((r)[9]),"=r"((r)[10]),"=r"((r)[11]),"=r"((r)[12]),"=r"((r)[13]),"=r"((r)[14]),"=r"((r)[15]), \
          "=r"((r)[16]),"=r"((r)[17]),"=r"((r)[18]),"=r"((r)[19]),"=r"((r)[20]),"=r"((r)[21]),"=r"((r)[22]),"=r"((r)[23]), \
          "=r"((r)[24]),"=r"((r)[25]),"=r"((r)[26]),"=r"((r)[27]),"=r"((r)[28]),"=r"((r)[29]),"=r"((r)[30]),"=r"((r)[31]) \
        : "r"(tmem_addr))

__device__ __forceinline__ void bulk_g2s(uint32_t dst, const void* src, uint32_t bytes, uint32_t mbar) {
    asm volatile("cp.async.bulk.shared::cta.global.mbarrier::complete_tx::bytes [%0], [%1], %2, [%3];"
                 :: "r"(dst), "l"(src), "r"(bytes), "r"(mbar) : "memory");
}

// cg2 TS-mode bf16 MMA: A in (each CTA's own) TMEM, B via SMEM descriptor
__device__ __forceinline__ void mma_f16_ts_cg2(uint32_t d_tmem, uint32_t a_tmem,
                                               uint64_t b_desc, uint32_t idesc, bool acc) {
    uint32_t en = acc ? 1u : 0u;
    asm volatile("{\n\t.reg .pred p;\n\tsetp.ne.u32 p, %5, 0;\n\t"
        "tcgen05.mma.cta_group::2.kind::f16 [%0], [%1], %2, %3, "
        "{%4, %4, %4, %4, %4, %4, %4, %4}, p;\n\t}"
        :: "r"(d_tmem), "r"(a_tmem), "l"(b_desc), "r"(idesc), "r"(0u), "r"(en)
        : "memory");
}

__device__ __forceinline__ uint64_t make_desc(uint32_t addr) {
    return (uint64_t(2) << 61) | (uint64_t(1) << 46) | (uint64_t(64) << 32)
         | (uint64_t(1) << 16) | ((addr >> 4) & 0x3FFF);
}

// idesc: F32 accum, bf16 A/B, M=256 (16<<24), N=64 (8<<17)
#define MMA_IDESC ((16u << 24) | (8u << 17) | (1u << 10) | (1u << 7) | (1u << 4))
#endif  // HAS_TCGEN05

__device__ __forceinline__ uint32_t smem_u32(const void* p) {
    uint32_t a;
    asm("{ .reg .u64 t; cvta.to.shared.u64 t, %1; cvt.u32.u64 %0, t; }" : "=r"(a) : "l"(p));
    return a;
}

// ============================================================
// Kernel 0: fp32 -> pre-swizzled 32-row bf16 tiles + exact row norms.
// One warp per row (2048 blocks x 256 threads), 4 float4 per lane
// for MLP=4 -> DRAM-bound instead of launch-bound.
// ============================================================
__global__ __launch_bounds__(256) void cvtsq_kernel(const float* __restrict__ X) {
    int warp = threadIdx.x >> 5;
    int lane = threadIdx.x & 31;
    int row = blockIdx.x * 8 + warp;
    const float4* xr = (const float4*)(X + (size_t)row * DIM);
    int tile = row >> 5, r = row & 31;
    char* tbase = (char*)g_xb + (size_t)tile * 32768;

    float s = 0.f;
#pragma unroll
    for (int i = 0; i < 4; ++i) {
        float4 v = xr[lane + 32 * i];
        s += v.x * v.x + v.y * v.y + v.z * v.z + v.w * v.w;
        uint32_t lo, hi;
        asm("cvt.rn.bf16x2.f32 %0, %1, %2;" : "=r"(lo) : "f"(v.y), "f"(v.x));
        asm("cvt.rn.bf16x2.f32 %0, %1, %2;" : "=r"(hi) : "f"(v.w), "f"(v.z));
        int k = (lane + 32 * i) * 4;
        uint32_t bo = (uint32_t)(r * 128 + (k & 63) * 2);
        uint32_t sw = bo ^ ((bo >> 3) & 0x70);
        *(uint2*)(tbase + (size_t)(k >> 6) * 4096 + sw) = make_uint2(lo, hi);
    }
#pragma unroll
    for (int o = 16; o > 0; o >>= 1) s += __shfl_down_sync(0xffffffffu, s, o);
    if (lane == 0) g_sq[row] = s;
}

// ============================================================
// Kernel 1: cg2 TS-mode bf16 GEMM, 4-deep TMEM D ring, 4-deep B ring,
// whole sq resident in SMEM. 64 clusters x 2 CTAs x 160 threads.
// Each CTA: 128 A rows in OWN TMEM; per 64-col tile u, rank r bulk-
// loads B rows [u*64 + r*32, +32) into slot u&3 (prefetch depth 3).
// Leader issues 32 cg2 TS MMAs -> D slot u&3; commit multicast.
// Epilogue: wait done -> LDTM -> EARLY dfree release -> min-screen top-3.
// ============================================================
__global__ __launch_bounds__(THREADS, 1) __cluster_dims__(2, 1, 1)
void mma_topk_kernel() {
    extern __shared__ char smem[];
    const uint32_t smem_base = smem_u32(smem);
    const int tid = threadIdx.x;
    const int rowBase = blockIdx.x * 128;
    const char* xb = (const char*)g_xb;

#if HAS_TCGEN05
    const int wid = tid >> 5;
    const int lane = tid & 31;
    const bool is_prod = (wid == 0);
    const int rank = blockIdx.x & 1;
    const int smsp = wid & 3;
    const int row = smsp * 32 + lane;

    if (is_prod) {
        TCGEN05_ALLOC_CG2(smem_base + SMEM_TPTR, 512);
        TCGEN05_RELINQ_CG2();
    }
    if (tid == 0) {
#pragma unroll
        for (int s = 0; s < 4; ++s) {
            MBARRIER_INIT(smem_base + SMEM_FULL0 + s * 8, 1);
            MBARRIER_INIT(smem_base + SMEM_DONE0 + s * 8, 1);
            MBARRIER_INIT(smem_base + SMEM_DFREE0 + s * 8, 4);
            MBARRIER_INIT(smem_base + SMEM_READY0 + s * 8, 1);
        }
        MBARRIER_INIT(smem_base + SMEM_SQFULL, 1);
    }
    __syncthreads();
    uint32_t tmem_base;
    asm volatile("ld.shared.b32 %0, [%1];" : "=r"(tmem_base) : "r"(smem_base + SMEM_TPTR));

    // ---- A fill: epilogue warps store own 128 rows x 512 bf16 to own TMEM,
    //      de-swizzling 16B granules from the pre-swizzled g_xb image ----
    if (!is_prod) {
        const int R = rowBase + row;
        const int tt = R >> 5, r = R & 31;
        const char* tbase = xb + (size_t)tt * 32768;
        uint32_t wo = (uint32_t)smsp << 21;
#pragma unroll
        for (int c8 = 0; c8 < 8; ++c8) {
            uint32_t rg[32];
#pragma unroll
            for (int u = 0; u < 8; ++u) {
                int g = c8 * 8 + u;                 // 16B granule index (k = g*8)
                uint32_t bo = (uint32_t)(r * 128 + (g & 7) * 16);
                uint32_t sw = bo ^ ((bo >> 3) & 0x70);
                uint4 v = *(const uint4*)(tbase + (size_t)(g >> 3) * 4096 + sw);
                rg[u * 4 + 0] = v.x; rg[u * 4 + 1] = v.y;
                rg[u * 4 + 2] = v.z; rg[u * 4 + 3] = v.w;
            }
            TCGEN05_ST_X32(tmem_base + TMEM_A + c8 * 32 + wo, rg);
        }
        TCGEN05_WAIT_ST();
        TCGEN05_FENCE_BEFORE();
    } else {
        // prologue: whole sq (64KB) + B tiles 0,1,2 (own 32-row halves)
        if (elect_one()) {
            MBARRIER_EXPECT_TX(smem_base + SMEM_SQFULL, 65536);
            bulk_g2s(smem_base + SMEM_SQ, (const char*)g_sq, 65536,
                     smem_base + SMEM_SQFULL);
#pragma unroll
            for (int pt = 0; pt < 3; ++pt) {
                uint32_t fb = smem_base + SMEM_FULL0 + pt * 8;
                MBARRIER_EXPECT_TX(fb, 32768);
                bulk_g2s(smem_base + SMEM_B + pt * 32768,
                         xb + (size_t)(2 * pt + rank) * 32768, 32768, fb);
            }
        }
    }
    __syncthreads();
    CLUSTER_SYNC();   // both CTAs' A in TMEM + mbarriers visible before any cg2 MMA

    if (is_prod) {
        for (int u = 0; u < NTILE; ++u) {
            const int ds = u & 3;
            MBARRIER_WAIT_PARITY(smem_base + SMEM_FULL0 + ds * 8, (u >> 2) & 1);
            if (u >= 4)
                MBARRIER_WAIT_PARITY(smem_base + SMEM_DFREE0 + ds * 8, ((u - 4) >> 2) & 1);

            if (rank == 1) {
                TCGEN05_FENCE_AFTER();
                if (elect_one())
                    MBARRIER_ARRIVE_LEADER(smem_base + SMEM_READY0 + ds * 8);
            } else {
                MBARRIER_WAIT_PARITY_CL(smem_base + SMEM_READY0 + ds * 8, (u >> 2) & 1);
                TCGEN05_FENCE_AFTER();
                if (elect_one()) {
                    uint64_t bdesc = make_desc(smem_base + SMEM_B + ds * 32768);
                    uint32_t dtm = tmem_base + TMEM_D + ds * 64;
#pragma unroll
                    for (int c = 0; c < 32; ++c) {
                        uint64_t boff = (uint64_t)((c >> 2) * 256 + (c & 3) * 2);
                        mma_f16_ts_cg2(dtm, tmem_base + TMEM_A + c * 8,
                                       bdesc + boff, MMA_IDESC, c > 0);
                    }
                    TCGEN05_COMMIT_MC_CG2(smem_base + SMEM_DONE0 + ds * 8);
                }
            }

            // recycle: B(u+3) -> slot (u+3)&3 == (u-1)&3, last read by MMA(u-1)
            if (u + 3 < NTILE) {
                if (u >= 1)
                    MBARRIER_WAIT_PARITY(smem_base + SMEM_DONE0 + ((u - 1) & 3) * 8,
                                         ((u - 1) >> 2) & 1);
                if (elect_one()) {
                    int s2 = (u + 3) & 3;
                    uint32_t fb = smem_base + SMEM_FULL0 + s2 * 8;
                    MBARRIER_EXPECT_TX(fb, 32768);
                    bulk_g2s(smem_base + SMEM_B + s2 * 32768,
                             xb + (size_t)(2 * (u + 3) + rank) * 32768, 32768, fb);
                }
            }
        }
    } else {
        // ---- epilogue warps: per-thread (one row) top-3 over all tiles ----
        MBARRIER_WAIT_PARITY(smem_base + SMEM_SQFULL, 0);
        const float* sqall = (const float*)(smem + SMEM_SQ);
        float v0 = FLT_MAX, v1 = FLT_MAX, v2 = FLT_MAX;
        int   i0 = 0, i1 = 0, i2 = 0;
        for (int u = 0; u < NTILE; ++u) {
            const int ds = u & 3;
            MBARRIER_WAIT_PARITY(smem_base + SMEM_DONE0 + ds * 8, (u >> 2) & 1);
            TCGEN05_FENCE_AFTER();
            const float* sqt = sqall + u * 64;
            const int colBase = u * 64;
            const uint32_t dtm = tmem_base + TMEM_D + ds * 64;
            uint32_t dr[64];
            TCGEN05_LD_X32(dr, dtm);
            TCGEN05_LD_X32(dr + 32, dtm + 32);
            TCGEN05_WAIT_LD();
            // EARLY release: D data fully in registers, sq is resident
            TCGEN05_FENCE_BEFORE();
            if (lane == 0) MBARRIER_ARRIVE(smem_base + SMEM_DFREE0 + ds * 8);
#pragma unroll
            for (int g = 0; g < 4; ++g) {
                float key[16];
#pragma unroll
                for (int c = 0; c < 16; ++c)
                    key[c] = fmaf(-2.f, __uint_as_float(dr[g * 16 + c]), sqt[g * 16 + c]);
                float t8[8];
#pragma unroll
                for (int c = 0; c < 8; ++c) t8[c] = fminf(key[c], key[c + 8]);
                float t4a = fminf(t8[0], t8[4]), t4b = fminf(t8[1], t8[5]);
                float t4c = fminf(t8[2], t8[6]), t4d = fminf(t8[3], t8[7]);
                float mn = fminf(fminf(t4a, t4b), fminf(t4c, t4d));
                if (mn < v2) {   // rare: exact ordered insert, ascending cols
#pragma unroll
                    for (int c = 0; c < 16; ++c) {
                        float k = key[c];
                        int col = colBase + g * 16 + c;
                        if (k < v2) {
                            if (k < v1) {
                                v2 = v1; i2 = i1;
                                if (k < v0) { v1 = v0; i1 = i0; v0 = k; i0 = col; }
                                else        { v1 = k; i1 = col; }
                            } else { v2 = k; i2 = col; }
                        }
                    }
                }
            }
        }
        g_neg[rowBase + row] = i2;
    }

    __syncthreads();
    CLUSTER_SYNC();   // peer MMA done reading my SMEM/TMEM before teardown
    if (is_prod) TCGEN05_DEALLOC_CG2(tmem_base, 512);
    CLUSTER_SYNC();

#else  // ---------------- SIMT fallback (non-'a' pass) ----------------
    // Reads the pre-swizzled 32-row-tile g_xb layout (per-4B de-swizzle).
    float* As = (float*)(smem);
    float* Bs = (float*)(smem + 4096);
    float* mv = (float*)(smem + 12288);
    int*   mi = (int*)(smem + 36864);
    const int tx = tid & 15, ty = tid >> 4;
    const bool act = (tid < 128);

    for (int half = 0; half < 2; ++half) {
        const int rh = rowBase + half * 64;
        float tv[8][3]; int tii[8][3];
#pragma unroll
        for (int i = 0; i < 8; ++i)
#pragma unroll
            for (int q = 0; q < 3; ++q) { tv[i][q] = FLT_MAX; tii[i][q] = 0x7fffffff; }

        for (int jt = 0; jt < NROW / 128; ++jt) {
            const int colBase = jt * 128;
            float c[8][8];
#pragma unroll
            for (int i = 0; i < 8; ++i)
#pragma unroll
                for (int j = 0; j < 8; ++j) c[i][j] = 0.f;

            for (int kt = 0; kt < DIM; kt += 16) {
                __syncthreads();
                if (act) {
#pragma unroll
                    for (int l = 0; l < 4; ++l) {
                        int f = tid + l * 128;
                        int r = f >> 3, uu = f & 7;
                        int R = rh + r, kk = kt + 2 * uu;
                        uint32_t bo = (uint32_t)((R & 31) * 128 + (kk & 63) * 2);
                        uint32_t sw = bo ^ ((bo >> 3) & 0x70);
                        uint32_t w = *(const uint32_t*)(xb + (size_t)(R >> 5) * 32768
                                                        + (size_t)(kk >> 6) * 4096 + sw);
                        __nv_bfloat162 b2 = *(__nv_bfloat162*)&w;
                        float2 f2 = __bfloat1622float2(b2);
                        As[(2 * uu + 0) * 64 + r] = f2.x;
                        As[(2 * uu + 1) * 64 + r] = f2.y;
                    }
#pragma unroll
                    for (int l = 0; l < 8; ++l) {
                        int f = tid + l * 128;
                        int r = f >> 3, uu = f & 7;
                        int R = colBase + r, kk = kt + 2 * uu;
                        uint32_t bo = (uint32_t)((R & 31) * 128 + (kk & 63) * 2);
                        uint32_t sw = bo ^ ((bo >> 3) & 0x70);
                        uint32_t w = *(const uint32_t*)(xb + (size_t)(R >> 5) * 32768
                                                        + (size_t)(kk >> 6) * 4096 + sw);
                        __nv_bfloat162 b2 = *(__nv_bfloat162*)&w;
                        float2 f2 = __bfloat1622float2(b2);
                        Bs[(2 * uu + 0) * 128 + r] = f2.x;
                        Bs[(2 * uu + 1) * 128 + r] = f2.y;
                    }
                }
                __syncthreads();
                if (act) {
#pragma unroll
                    for (int kk = 0; kk < 16; ++kk) {
                        float a[8], b[8];
#pragma unroll
                        for (int i = 0; i < 8; ++i) a[i] = As[kk * 64 + ty * 8 + i];
#pragma unroll
                        for (int j = 0; j < 8; ++j) b[j] = Bs[kk * 128 + tx * 8 + j];
#pragma unroll
                        for (int i = 0; i < 8; ++i)
#pragma unroll
                            for (int j = 0; j < 8; ++j) c[i][j] += a[i] * b[j];
                    }
                }
            }
            if (act) {
#pragma unroll
                for (int j = 0; j < 8; ++j) {
                    int col = colBase + tx * 8 + j;
                    float sqc = g_sq[col];
#pragma unroll
                    for (int i = 0; i < 8; ++i) {
                        float d2 = fmaf(-2.f, c[i][j], sqc);
                        bool b2c = (d2 < tv[i][2]) || (d2 == tv[i][2] && col < tii[i][2]);
                        if (b2c) {
                            bool b1c = (d2 < tv[i][1]) || (d2 == tv[i][1] && col < tii[i][1]);
                            bool b0c = (d2 < tv[i][0]) || (d2 == tv[i][0] && col < tii[i][0]);
                            if (b0c) {
                                tv[i][2] = tv[i][1]; tii[i][2] = tii[i][1];
                                tv[i][1] = tv[i][0]; tii[i][1] = tii[i][0];
                                tv[i][0] = d2;       tii[i][0] = col;
                            } else if (b1c) {
                                tv[i][2] = tv[i][1]; tii[i][2] = tii[i][1];
                                tv[i][1] = d2;       tii[i][1] = col;
                            } else { tv[i][2] = d2; tii[i][2] = col; }
                        }
                    }
                }
            }
        }

        __syncthreads();
        if (act) {
#pragma unroll
            for (int i = 0; i < 8; ++i)
#pragma unroll
                for (int q = 0; q < 3; ++q) {
                    mv[(ty * 8 + i) * 48 + tx * 3 + q] = tv[i][q];
                    mi[(ty * 8 + i) * 48 + tx * 3 + q] = tii[i][q];
                }
        }
        __syncthreads();
        if (tid < 64) {
            float w0 = FLT_MAX, w1 = FLT_MAX, w2 = FLT_MAX;
            int   j0 = 0x7fffffff, j1 = 0x7fffffff, j2 = 0x7fffffff;
            for (int cnd = 0; cnd < 48; ++cnd) {
                float d = mv[tid * 48 + cnd];
                int   ix = mi[tid * 48 + cnd];
                bool b2c = (d < w2) || (d == w2 && ix < j2);
                if (b2c) {
                    bool b1c = (d < w1) || (d == w1 && ix < j1);
                    bool b0c = (d < w0) || (d == w0 && ix < j0);
                    if (b0c)      { w2 = w1; j2 = j1; w1 = w0; j1 = j0; w0 = d; j0 = ix; }
                    else if (b1c) { w2 = w1; j2 = j1; w1 = d; j1 = ix; }
                    else          { w2 = d;  j2 = ix; }
                }
            }
            g_neg[rh + tid] = j2;
        }
        __syncthreads();
    }
#endif
}

// ============================================================
// Kernel 2: per-row triplet loss (one warp per row) + fused
// deterministic mean reduction in the last-arriving block.
// ============================================================
__global__ __launch_bounds__(256) void rowloss_kernel(const float* __restrict__ X,
                                                      const float* __restrict__ P,
                                                      float* __restrict__ out) {
    int warp = threadIdx.x >> 5;
    int lane = threadIdx.x & 31;
    int row = blockIdx.x * 8 + warp;
    const float4* xr = (const float4*)(X + (size_t)row * DIM);
    const float4* pr = (const float4*)(P + (size_t)row * DIM);
    const float4* nr = (const float4*)(X + (size_t)g_neg[row] * DIM);
    float sap = 0.f, san = 0.f;
#pragma unroll
    for (int i = 0; i < 4; ++i) {
        float4 x = xr[lane + 32 * i];
        float4 p = pr[lane + 32 * i];
        float4 v = nr[lane + 32 * i];
        float d;
        d = x.x - p.x + EPSV; sap += d * d;
        d = x.y - p.y + EPSV; sap += d * d;
        d = x.z - p.z + EPSV; sap += d * d;
        d = x.w - p.w + EPSV; sap += d * d;
        d = x.x - v.x + EPSV; san += d * d;
        d = x.y - v.y + EPSV; san += d * d;
        d = x.z - v.z + EPSV; san += d * d;
        d = x.w - v.w + EPSV; san += d * d;
    }
#pragma unroll
    for (int o = 16; o > 0; o >>= 1) {
        sap += __shfl_down_sync(0xffffffffu, sap, o);
        san += __shfl_down_sync(0xffffffffu, san, o);
    }
    if (lane == 0)
        g_rowloss[row] = fmaxf(sqrtf(sap) - sqrtf(san) + MARGIN, 0.f);

    __shared__ bool s_last;
    __threadfence();
    __syncthreads();
    if (threadIdx.x == 0) {
        int done = atomicAdd(&g_blkdone, 1);
        s_last = (done == gridDim.x - 1);
    }
    __syncthreads();
    if (s_last) {
        int t = threadIdx.x;
        float s = 0.f;
        for (int i = t; i < NROW; i += 256) s += g_rowloss[i];
#pragma unroll
        for (int o = 16; o > 0; o >>= 1) s += __shfl_down_sync(0xffffffffu, s, o);
        __shared__ float ws[8];
        if ((t & 31) == 0) ws[t >> 5] = s;
        __syncthreads();
        if (t == 0) {
            float tot = 0.f;
#pragma unroll
            for (int w = 0; w < 8; ++w) tot += ws[w];
            out[0] = tot / (float)NROW;
            g_blkdone = 0;      // reset for next graph replay
        }
    }
}

extern "C" void kernel_launch(void* const* d_in, const int* in_sizes, int n_in,
                              void* d_out, int out_size) {
    const float* X = (const float*)d_in[0];   // inputs  [16384, 512] f32
    const float* P = (const float*)d_in[1];   // positive[16384, 512] f32
    float* out = (float*)d_out;

    cudaFuncSetAttribute(mma_topk_kernel,
                         cudaFuncAttributeMaxDynamicSharedMemorySize, SMEM_TOTAL);

    cvtsq_kernel<<<NROW / 8, 256>>>(X);
    mma_topk_kernel<<<128, THREADS, SMEM_TOTAL>>>();
    rowloss_kernel<<<NROW / 8, 256>>>(X, P, out);
}